// round 17
// baseline (speedup 1.0000x reference)
#include <cuda_runtime.h>
#include <cstdint>

#define BATCH   4096
#define SEQ     32
#define DIM     256
#define VOCAB   50257
#define NALIVE  100

// Grid layout: 20480 worker blocks (every 5th = ctx, rest fill, as in the
// best-measured R12 kernel) + 16 fixup blocks appended at the END of the
// grid. Fixup blocks dispatch last, gate on a ctx-completion counter, and
// retire inside the fill tail's shadow — no second kernel, no launch gap.
#define RATIO   5
#define NCTX    4096
#define NZB     16384
#define NWORK   20480
#define NFIX    16
#define NBTOT   20496
#define TOTAL4  51463168  // BATCH*VOCAB/4

// Scratch: compacted nonzero activations per row (empty in practice).
__device__ float g_val[BATCH * NALIVE];
__device__ int   g_idx[BATCH * NALIVE];
__device__ int   g_cnt[BATCH];
// Completion counters (zero-init; restored to zero every replay by the
// last fixup block, so the captured graph replays deterministically).
__device__ int   g_ctx_done;
__device__ int   g_all_done;
__device__ int   g_fix_done;

__device__ __forceinline__ float warp_sum(float v) {
    #pragma unroll
    for (int off = 16; off > 0; off >>= 1)
        v += __shfl_xor_sync(0xFFFFFFFFu, v, off);
    return v;
}
__device__ __forceinline__ float warp_max(float v) {
    #pragma unroll
    for (int off = 16; off > 0; off >>= 1)
        v = fmaxf(v, __shfl_xor_sync(0xFFFFFFFFu, v, off));
    return v;
}

__global__ __launch_bounds__(256, 8)
void geometric_lm_kernel(const int*   __restrict__ tok,
                         const float* __restrict__ te,
                         const float* __restrict__ pe,
                         const float* __restrict__ q,
                         const float* __restrict__ pos,
                         const float* __restrict__ W,
                         float*       __restrict__ out) {
    const int bid = blockIdx.x;
    const int tid = threadIdx.x;            // 0..255

    if (bid < NWORK && (bid % RATIO) != 0) {
        // ---------------- zero-fill role (16384 blocks) ----------------
        const int zid = bid - (bid / RATIO + 1);         // 0..16383
        const float4 z = make_float4(0.f, 0.f, 0.f, 0.f);
        float4* __restrict__ o4 = (float4*)out;
        const long stride = (long)NZB * 256;
        for (long i = (long)zid * 256 + tid; i < (long)TOTAL4; i += stride)
            __stcs(o4 + i, z);
        __syncthreads();
        if (tid == 0) { __threadfence(); atomicAdd(&g_all_done, 1); }
        return;
    }

    if (bid < NWORK) {
        // ---------------- ctx role (4096 blocks, b = bid/5) ----------------
        const int b = bid / RATIO;

        __shared__ float s_q[DIM];        // 1 KB
        __shared__ float s_ctx[DIM];      // 1 KB
        __shared__ float s_score[SEQ];
        __shared__ float s_w[SEQ];
        __shared__ float s_act[NALIVE];
        __shared__ int   s_tok[SEQ];

        const int lane = tid & 31;
        const int wid  = tid >> 5;             // 0..7

        s_q[tid] = q[tid];
        if (tid < SEQ) s_tok[tid] = tok[b * SEQ + tid];
        __syncthreads();

        // Phase B: attention scores, embeds read from global/L2 on the fly.
        #pragma unroll
        for (int s = wid; s < SEQ; s += 8) {
            const float* __restrict__ trow = te + (size_t)s_tok[s] * DIM;
            const float* __restrict__ prow = pe + s * DIM;
            float p = 0.f;
            #pragma unroll
            for (int i = 0; i < 8; i++) {
                int d = lane + 32 * i;
                p = fmaf(__ldg(trow + d) + __ldg(prow + d), s_q[d], p);
            }
            p = warp_sum(p);
            if (lane == 0) s_score[s] = p * (1.0f / 16.0f);   // / sqrt(256)
        }
        __syncthreads();

        // Phase C: softmax over S=32 (warp 0, one score per lane)
        if (wid == 0) {
            float sc = s_score[lane];
            float m  = warp_max(sc);
            float e  = expf(sc - m);
            float s  = warp_sum(e);
            s_w[lane] = e / s;
        }
        __syncthreads();

        // Phase D: context[d] = sum_s w[s]*(te+pe)  (L2-warm reread)
        {
            const int d = tid;
            float c = 0.f;
            #pragma unroll
            for (int s = 0; s < SEQ; s++) {
                float e = __ldg(te + (size_t)s_tok[s] * DIM + d) + __ldg(pe + s * DIM + d);
                c = fmaf(s_w[s], e, c);
            }
            s_ctx[d] = c;
        }
        __syncthreads();

        // Phase E: RBF distances to 100 positions
        for (int j = wid; j < NALIVE; j += 8) {
            float p = 0.f;
            #pragma unroll
            for (int i = 0; i < 8; i++) {
                int d = lane + 32 * i;
                float df = s_ctx[d] - __ldg(pos + j * DIM + d);
                p = fmaf(df, df, p);
            }
            p = warp_sum(p);
            if (lane == 0) s_act[j] = expf(-2.0f * p);   // exp(-d2/(2*0.5^2))
        }
        __syncthreads();

        // Phase F: normalize + compact nonzeros (warp 0)
        if (wid == 0) {
            float sum = 0.f;
            for (int j = lane; j < NALIVE; j += 32) sum += s_act[j];
            sum = warp_sum(sum);
            const float denom = sum + 1e-8f;

            int cnt = 0;
            #pragma unroll
            for (int base = 0; base < 128; base += 32) {
                const int j = base + lane;
                float a = 0.f;
                bool nz = false;
                if (j < NALIVE) {
                    a  = s_act[j] / denom;
                    nz = (a != 0.0f);
                }
                const unsigned m = __ballot_sync(0xFFFFFFFFu, nz);
                const int pre = __popc(m & ((1u << lane) - 1u));
                if (nz) {
                    g_val[b * NALIVE + cnt + pre] = a;
                    g_idx[b * NALIVE + cnt + pre] = j;
                }
                cnt += __popc(m);
            }
            if (lane == 0) g_cnt[b] = cnt;
        }
        __syncthreads();
        if (tid == 0) {
            __threadfence();                 // publish g_cnt/g_val/g_idx
            atomicAdd(&g_ctx_done, 1);
            atomicAdd(&g_all_done, 1);
        }
        return;
    }

    // ---------------- fixup role (16 blocks, dispatched LAST) --------------
    {
        __shared__ int   s_cnt_arr[256];
        __shared__ float s_val[NALIVE];
        __shared__ int   s_idx[NALIVE];

        const int b0 = (bid - NWORK) * 256;

        // Gate 1: all ctx blocks have published (in practice: zero spins,
        // ctx blocks finish long before these last-dispatched blocks start).
        if (tid == 0) {
            while (atomicAdd(&g_ctx_done, 0) < NCTX) { }
            __threadfence();
        }
        __syncthreads();

        const int mycnt = g_cnt[b0 + tid];
        s_cnt_arr[tid] = mycnt;
        const int nz = __syncthreads_count(mycnt != 0);

        if (nz != 0) {
            // Rare path: wait for ALL worker blocks (fill writes to these rows
            // must be complete before we overwrite them).
            if (tid == 0) {
                while (atomicAdd(&g_all_done, 0) < NWORK) { }
                __threadfence();
            }
            __syncthreads();

            for (int r = 0; r < 256; r++) {
                const int cnt = s_cnt_arr[r];
                if (cnt == 0) continue;
                const int b = b0 + r;

                if (tid < cnt) {
                    s_val[tid] = g_val[b * NALIVE + tid];
                    s_idx[tid] = g_idx[b * NALIVE + tid];
                }
                __syncthreads();

                float* __restrict__ orow = out + (size_t)b * VOCAB;
                for (int v = tid; v < VOCAB; v += 256) {
                    float acc = 0.f;
                    for (int k = 0; k < cnt; k++)
                        acc = fmaf(s_val[k], W[(size_t)s_idx[k] * VOCAB + v], acc);
                    orow[v] = acc;
                }
                __syncthreads();
            }
        }

        // Reset counters for the next graph replay (last fixup block only;
        // atomics commute, so in-flight fill increments net to zero).
        __syncthreads();
        if (tid == 0) {
            const int t = atomicAdd(&g_fix_done, 1);
            if (t == NFIX - 1) {
                atomicSub(&g_ctx_done, NCTX);
                atomicSub(&g_all_done, NWORK);
                atomicExch(&g_fix_done, 0);
            }
        }
    }
}

extern "C" void kernel_launch(void* const* d_in, const int* in_sizes, int n_in,
                              void* d_out, int out_size) {
    const int*   tok = (const int*)  d_in[0];   // [B, S]
    const float* te  = (const float*)d_in[1];   // [V, D]
    const float* pe  = (const float*)d_in[2];   // [S, D]
    const float* q   = (const float*)d_in[3];   // [D]
    const float* pos = (const float*)d_in[4];   // [N, D]
    const float* W   = (const float*)d_in[5];   // [N, V]
    float* out = (float*)d_out;                 // [B, V]

    geometric_lm_kernel<<<NBTOT, 256>>>(tok, te, pe, q, pos, W, out);
}